// round 3
// baseline (speedup 1.0000x reference)
#include <cuda_runtime.h>
#include <cstdint>

#define GENE   2000
#define TE     128
#define HID    2048
#define KIN    2128      // GENE + TE (time embedding lives in x tail)
#define NSTEP  256
#define GRID   256
#define BLOCK  256
#define NCOL   8         // output columns per CTA
#define DT     (1.0f/255.0f)
#define CHUNK  512                         // weight rows per cp.async chunk
#define NBUF   3
#define BUF_FLOATS (CHUNK*NCOL)            // 4096 floats = 16 KB
#define SMEM_FLOATS (2176 + NBUF*BUF_FLOATS)
#define SMEM_BYTES  (SMEM_FLOATS*4)

// Persistent scratch (device globals: allocation is forbidden)
__device__ float    g_x[2][2176];      // x ping-pong: [0,2000)=x, [2000,2128)=te(t)
__device__ float    g_h0[HID];
__device__ float    g_h1[HID];
__device__ float    g_te[NSTEP][TE];   // precomputed time embeddings
__device__ unsigned g_count;           // grid-barrier monotonic counter

// ---------------------------------------------------------------------------
// Grid barrier: monotonic counter, release-arrive + acquire-spin.
// ---------------------------------------------------------------------------
__device__ __forceinline__ void grid_barrier(unsigned& nbar) {
    __syncthreads();
    ++nbar;
    if (threadIdx.x == 0) {
        __threadfence();
        asm volatile("red.release.gpu.add.u32 [%0], 1;" :: "l"(&g_count) : "memory");
        const unsigned target = nbar * GRID;
        unsigned cur;
        do {
            asm volatile("ld.acquire.gpu.u32 %0, [%1];" : "=r"(cur) : "l"(&g_count) : "memory");
        } while (cur < target);
    }
    __syncthreads();
}

// ---------------------------------------------------------------------------
// cp.async helpers
// ---------------------------------------------------------------------------
__device__ __forceinline__ void cp16(float* dst, const float* src) {
    unsigned a = (unsigned)__cvta_generic_to_shared(dst);
    asm volatile("cp.async.cg.shared.global [%0], [%1], 16;" :: "r"(a), "l"(src));
}
__device__ __forceinline__ void commit() {
    asm volatile("cp.async.commit_group;");
}

// One CHUNK-row x NCOL-col slice -> smem buf; always exactly one commit.
__device__ __forceinline__ void prefetch_chunk(const float* __restrict__ W,
        int K, int O, int j0, int base, float* __restrict__ buf, int tid) {
    if (j0 < O) {
        #pragma unroll
        for (int i = 0; i < (CHUNK*2)/BLOCK; ++i) {      // 2 x 16B segs per row
            int s = tid + i*BLOCK;
            int r = s >> 1, c = s & 1;
            if (base + r < K)
                cp16(buf + r*NCOL + c*4, W + (long)(base + r)*O + j0 + c*4);
        }
    }
    commit();
}

// ---------------------------------------------------------------------------
// Generic layer. Invariant: chunk0 of THIS layer was already issued (oldest
// pending group). On exit, chunk0 of NEXT layer is issued. Depth-3 rotation:
// issue slot `is` and read slot `rs` advance identically over real chunks.
// Result valid for tid<2 (float4 at columns j0 + tid*4).
// ---------------------------------------------------------------------------
__device__ __forceinline__ float4 layer_core(
    const float* __restrict__ W,  int K,  int O,
    const float* __restrict__ Wn, int Kn, int On,
    const float* __restrict__ in,
    float* __restrict__ xs, float* __restrict__ bufs,
    int& is, int& rs, float4 (*red)[2],
    int j0, int tid, unsigned& nbar)
{
    grid_barrier(nbar);

    // Issue chunks 1 and 2 of this layer (all layers have >=4 chunks)
    prefetch_chunk(W, K, O, j0, 1*CHUNK, bufs + is*BUF_FLOATS, tid);
    if (++is == NBUF) is = 0;
    prefetch_chunk(W, K, O, j0, 2*CHUNK, bufs + is*BUF_FLOATS, tid);
    if (++is == NBUF) is = 0;

    // Stage input vector (L2 path — produced by other SMs)
    const int K4 = K >> 2;
    for (int i = tid; i < K4; i += BLOCK)
        reinterpret_cast<float4*>(xs)[i] =
            __ldcg(reinterpret_cast<const float4*>(in) + i);

    const int kw = tid >> 1;           // 0..127
    const int jv = tid & 1;            // which float4 of the 8 cols
    float4 acc = make_float4(0.f, 0.f, 0.f, 0.f);

    const int nc = (K + CHUNK - 1) / CHUNK;
    for (int c = 0; c < nc; ++c) {
        asm volatile("cp.async.wait_group 2;");
        __syncthreads();               // chunk c visible to all (also covers xs)

        if (j0 < O) {
            const float* __restrict__ buf = bufs + rs*BUF_FLOATS;
            const int base = c * CHUNK;
            const int rows = min(CHUNK, K - base);
            #pragma unroll
            for (int i = 0; i < CHUNK/(BLOCK/2); ++i) {
                const int r = kw + i*(BLOCK/2);
                if (r < rows) {
                    const float  xv = xs[base + r];
                    const float4 w  = *reinterpret_cast<const float4*>(buf + r*NCOL + jv*4);
                    acc.x = fmaf(xv, w.x, acc.x);
                    acc.y = fmaf(xv, w.y, acc.y);
                    acc.z = fmaf(xv, w.z, acc.z);
                    acc.w = fmaf(xv, w.w, acc.w);
                }
            }
        }
        if (++rs == NBUF) rs = 0;
        __syncthreads();               // all reads of this buffer done

        const int k = c + NBUF;
        if (k < nc) {
            prefetch_chunk(W, K, O, j0, k*CHUNK, bufs + is*BUF_FLOATS, tid);
            if (++is == NBUF) is = 0;
        } else if (k == nc) {
            prefetch_chunk(Wn, Kn, On, j0, 0, bufs + is*BUF_FLOATS, tid);
            if (++is == NBUF) is = 0;
        } else {
            commit();                  // dummy: keep group counts uniform
        }
    }

    // Warp reduce over kw bits inside the warp (lane bits 1..4)
    #pragma unroll
    for (int m = 2; m <= 16; m <<= 1) {
        acc.x += __shfl_xor_sync(0xffffffffu, acc.x, m);
        acc.y += __shfl_xor_sync(0xffffffffu, acc.y, m);
        acc.z += __shfl_xor_sync(0xffffffffu, acc.z, m);
        acc.w += __shfl_xor_sync(0xffffffffu, acc.w, m);
    }
    const int warp = tid >> 5;
    const int lane = tid & 31;
    if (lane < 2) red[warp][lane] = acc;
    __syncthreads();

    float4 r = make_float4(0.f, 0.f, 0.f, 0.f);
    if (tid < 16) {                    // 8 warps x 2 jv
        const int wi = tid >> 1;
        const int j  = tid & 1;
        r = red[wi][j];
        #pragma unroll
        for (int m = 2; m <= 8; m <<= 1) {
            r.x += __shfl_xor_sync(0xffffu, r.x, m);
            r.y += __shfl_xor_sync(0xffffu, r.y, m);
            r.z += __shfl_xor_sync(0xffffu, r.z, m);
            r.w += __shfl_xor_sync(0xffffu, r.w, m);
        }
    }
    return r;   // valid for tid < 2
}

__device__ __forceinline__ void store_hidden(float4 r,
        const float* __restrict__ bias, int O, float* __restrict__ out,
        int j0, int tid)
{
    if (tid < 2 && j0 < O) {
        const float4 b = __ldg(reinterpret_cast<const float4*>(bias + j0) + tid);
        r.x = fmaxf(r.x + b.x, 0.f);
        r.y = fmaxf(r.y + b.y, 0.f);
        r.z = fmaxf(r.z + b.z, 0.f);
        r.w = fmaxf(r.w + b.w, 0.f);
        reinterpret_cast<float4*>(out + j0)[tid] = r;
    }
}

// ---------------------------------------------------------------------------
// Init: reset barrier, seed x0 (+te(1) tail) + trajectory row 0, precompute te.
// ---------------------------------------------------------------------------
__global__ void init_kernel(
    const float* __restrict__ start,
    const float* __restrict__ te_w1, const float* __restrict__ te_b1,
    const float* __restrict__ te_w2, const float* __restrict__ te_b2,
    float* __restrict__ out)
{
    const int b   = blockIdx.x;     // 0..255
    const int tid = threadIdx.x;    // 128 threads
    if (b == 0) {
        if (tid == 0) g_count = 0u;
        for (int k = tid; k < GENE; k += TE) {
            const float v = start[k];
            g_x[0][k] = v;
            out[k]    = v;          // trajectory row 0
        }
    } else {
        const float t = (float)b * DT;
        __shared__ float h[TE];
        h[tid] = fmaxf(fmaf(t, te_w1[tid], te_b1[tid]), 0.f);
        __syncthreads();
        float acc = te_b2[tid];
        #pragma unroll 8
        for (int k = 0; k < TE; ++k)
            acc = fmaf(h[k], te_w2[k * TE + tid], acc);
        g_te[b][tid] = acc;
        if (b == 1) g_x[0][GENE + tid] = acc;   // te(1) tail for step 1
    }
}

// ---------------------------------------------------------------------------
// Persistent kernel: 255 Euler steps, 6 grid barriers/step, depth-3 cp.async
// weight streaming, 2 CTAs per SM.
// ---------------------------------------------------------------------------
__global__ void __launch_bounds__(BLOCK, 2) bridge_kernel(
    const float* __restrict__ w0, const float* __restrict__ b0,
    const float* __restrict__ w1, const float* __restrict__ b1,
    const float* __restrict__ w2, const float* __restrict__ b2,
    const float* __restrict__ w3, const float* __restrict__ b3,
    const float* __restrict__ w4, const float* __restrict__ b4,
    const float* __restrict__ wout, const float* __restrict__ bout,
    float* __restrict__ out)
{
    extern __shared__ float smem[];
    float* xs   = smem;                 // 2176 floats
    float* bufs = smem + 2176;          // NBUF * BUF_FLOATS
    __shared__ float4 red[8][2];

    const int tid = threadIdx.x;
    const int j0  = blockIdx.x * NCOL;
    unsigned nbar = 0;
    int is = 0, rs = 0;

    // Prologue: chunk0 of step-1 layer0
    prefetch_chunk(w0, KIN, HID, j0, 0, bufs, tid);
    if (++is == NBUF) is = 0;

    for (int t = 1; t < NSTEP; ++t) {
        const float* xprev = g_x[(t - 1) & 1];
        float*       xcur  = g_x[t & 1];
        float4 r;

        r = layer_core(w0, KIN, HID,  w1, HID, HID,  xprev,
                       xs, bufs, is, rs, red, j0, tid, nbar);
        store_hidden(r, b0, HID, g_h0, j0, tid);

        r = layer_core(w1, HID, HID,  w2, HID, HID,  g_h0,
                       xs, bufs, is, rs, red, j0, tid, nbar);
        store_hidden(r, b1, HID, g_h1, j0, tid);

        r = layer_core(w2, HID, HID,  w3, HID, HID,  g_h1,
                       xs, bufs, is, rs, red, j0, tid, nbar);
        store_hidden(r, b2, HID, g_h0, j0, tid);

        r = layer_core(w3, HID, HID,  w4, HID, HID,  g_h0,
                       xs, bufs, is, rs, red, j0, tid, nbar);
        store_hidden(r, b3, HID, g_h1, j0, tid);

        r = layer_core(w4, HID, HID,  wout, HID, GENE,  g_h1,
                       xs, bufs, is, rs, red, j0, tid, nbar);
        store_hidden(r, b4, HID, g_h0, j0, tid);

        // Final layer + Euler update + trajectory store
        r = layer_core(wout, HID, GENE,  w0, KIN, HID,  g_h0,
                       xs, bufs, is, rs, red, j0, tid, nbar);
        if (tid < 2 && j0 < GENE) {
            const float4 b  = __ldg(reinterpret_cast<const float4*>(bout + j0) + tid);
            const float4 xp = __ldcg(reinterpret_cast<const float4*>(xprev + j0) + tid);
            float4 xn;
            xn.x = fmaf(r.x + b.x, DT, xp.x);
            xn.y = fmaf(r.y + b.y, DT, xp.y);
            xn.z = fmaf(r.z + b.z, DT, xp.z);
            xn.w = fmaf(r.w + b.w, DT, xp.w);
            reinterpret_cast<float4*>(xcur + j0)[tid] = xn;
            reinterpret_cast<float4*>(out + (size_t)t * GENE + j0)[tid] = xn;
        }
        // idle tail CTA installs te(t+1) into xcur tail for next step's layer0
        if (blockIdx.x == GRID - 1 && t + 1 < NSTEP && tid < TE)
            xcur[GENE + tid] = g_te[t + 1][tid];
    }
}

extern "C" void kernel_launch(void* const* d_in, const int* in_sizes, int n_in,
                              void* d_out, int out_size)
{
    (void)in_sizes; (void)n_in; (void)out_size;
    const float* start  = (const float*)d_in[0];
    // d_in[1] = end_state (unused)
    const float* te_w1  = (const float*)d_in[2];
    const float* te_b1  = (const float*)d_in[3];
    const float* te_w2  = (const float*)d_in[4];
    const float* te_b2  = (const float*)d_in[5];
    const float* w0     = (const float*)d_in[6];
    const float* b0     = (const float*)d_in[7];
    const float* w1     = (const float*)d_in[8];
    const float* b1     = (const float*)d_in[9];
    const float* w2     = (const float*)d_in[10];
    const float* b2     = (const float*)d_in[11];
    const float* w3     = (const float*)d_in[12];
    const float* b3     = (const float*)d_in[13];
    const float* w4     = (const float*)d_in[14];
    const float* b4     = (const float*)d_in[15];
    const float* wout   = (const float*)d_in[16];
    const float* bout   = (const float*)d_in[17];
    float* out = (float*)d_out;

    cudaFuncSetAttribute(bridge_kernel,
                         cudaFuncAttributeMaxDynamicSharedMemorySize, SMEM_BYTES);

    init_kernel<<<NSTEP, TE>>>(start, te_w1, te_b1, te_w2, te_b2, out);
    bridge_kernel<<<GRID, BLOCK, SMEM_BYTES>>>(w0, b0, w1, b1, w2, b2, w3, b3,
                                               w4, b4, wout, bout, out);
}

// round 4
// speedup vs baseline: 1.2082x; 1.2082x over previous
#include <cuda_runtime.h>
#include <cstdint>

#define GENE   2000
#define TE     128
#define HID    2048
#define KIN    2128      // GENE + TE (time embedding lives in x tail)
#define NSTEP  256
#define GRID   128
#define BLOCK  512
#define NCOL   16        // output columns per CTA
#define DT     (1.0f/255.0f)
#define CHUNK  512
#define NBUF   4
#define LOOKAHEAD 3                         // NBUF-1 chunks issued ahead
#define BUF_FLOATS (CHUNK*NCOL)             // 8192 floats = 32 KB
#define SMEM_FLOATS (2176 + NBUF*BUF_FLOATS)
#define SMEM_BYTES  (SMEM_FLOATS*4)
#define LEAVES 16
#define PER_LEAF (GRID/LEAVES)              // 8

// Persistent scratch (device globals: allocation is forbidden)
__device__ float    g_x[2][2176];      // x ping-pong: [0,2000)=x, [2000,2128)=te(t)
__device__ float    g_h0[HID];
__device__ float    g_h1[HID];
__device__ float    g_te[NSTEP][TE];   // precomputed time embeddings
__device__ unsigned g_leaf[LEAVES];    // tree-barrier leaf counters
__device__ unsigned g_root;            // tree-barrier root counter

// ---------------------------------------------------------------------------
// Grid barrier: two-level tree (16 leaves x 8 arrivals), monotonic counters.
// acq_rel leaf RMW + release root arrive + acquire root poll => full chain.
// ---------------------------------------------------------------------------
__device__ __forceinline__ void grid_barrier(unsigned& nbar) {
    __syncthreads();
    ++nbar;
    if (threadIdx.x == 0) {
        unsigned old;
        asm volatile("atom.acq_rel.gpu.global.add.u32 %0, [%1], 1;"
                     : "=r"(old) : "l"(&g_leaf[blockIdx.x & (LEAVES-1)]) : "memory");
        if (old == nbar * PER_LEAF - 1)
            asm volatile("red.release.gpu.global.add.u32 [%0], 1;"
                         :: "l"(&g_root) : "memory");
        const unsigned target = nbar * LEAVES;
        unsigned cur;
        do {
            asm volatile("ld.acquire.gpu.global.u32 %0, [%1];"
                         : "=r"(cur) : "l"(&g_root) : "memory");
        } while (cur < target);
    }
    __syncthreads();
}

// ---------------------------------------------------------------------------
// cp.async helpers
// ---------------------------------------------------------------------------
__device__ __forceinline__ void cp16(float* dst, const float* src) {
    unsigned a = (unsigned)__cvta_generic_to_shared(dst);
    asm volatile("cp.async.cg.shared.global [%0], [%1], 16;" :: "r"(a), "l"(src));
}

// One CHUNK x NCOL weight slice -> smem buf; exactly one commit (all threads).
__device__ __forceinline__ void prefetch_chunk(const float* __restrict__ W,
        int K, int O, int j0, int base, float* __restrict__ buf, int tid) {
    if (j0 < O) {
        #pragma unroll
        for (int i = 0; i < (CHUNK*(NCOL/4))/BLOCK; ++i) {   // 4 segs/thread
            int s = tid + i*BLOCK;
            int r = s >> 2, c = s & 3;
            if (base + r < K)
                cp16(buf + r*NCOL + c*4, W + (long)(base + r)*O + j0 + c*4);
        }
    }
    asm volatile("cp.async.commit_group;");
}

// ---------------------------------------------------------------------------
// Layer. Invariant: on entry, this layer's chunks 0..2 are already in flight
// (issued during the previous layer / prologue). During its nc iterations it
// issues its own chunks 3..nc-1, then chunks 0..2 of the NEXT layer.
// One wait_group + one __syncthreads per chunk. Result valid for tid<4.
// ---------------------------------------------------------------------------
__device__ __forceinline__ float4 layer_core(
    const float* __restrict__ W,  int K,  int O,
    const float* __restrict__ Wn, int Kn, int On,
    const float* __restrict__ in,
    float* __restrict__ xs, float* __restrict__ bufs,
    int& is, int& rs, float4 (*red)[4],
    int j0, int tid, unsigned& nbar)
{
    grid_barrier(nbar);

    // Stage input vector (fresh data from other SMs -> L2 path). The STS
    // drain of the first in-loop __syncthreads makes xs visible.
    const int K4 = K >> 2;
    for (int i = tid; i < K4; i += BLOCK)
        reinterpret_cast<float4*>(xs)[i] =
            __ldcg(reinterpret_cast<const float4*>(in) + i);

    const int kw = tid >> 2;
    const int jv = tid & 3;
    float4 acc = make_float4(0.f, 0.f, 0.f, 0.f);

    const int nc = (K + CHUNK - 1) / CHUNK;
    for (int c = 0; c < nc; ++c) {
        asm volatile("cp.async.wait_group 2;");   // chunk c landed
        __syncthreads();                          // ..and chunk c-1 reads done

        // Refill the buffer freed by the sync (chunk c-1's slot).
        if (c < nc - LOOKAHEAD)
            prefetch_chunk(W,  K,  O,  j0, (c + LOOKAHEAD)*CHUNK,
                           bufs + is*BUF_FLOATS, tid);
        else
            prefetch_chunk(Wn, Kn, On, j0, (c - (nc - LOOKAHEAD))*CHUNK,
                           bufs + is*BUF_FLOATS, tid);
        if (++is == NBUF) is = 0;

        if (j0 < O) {
            const float* __restrict__ buf = bufs + rs*BUF_FLOATS;
            const int base = c * CHUNK;
            const int rows = min(CHUNK, K - base);
            #pragma unroll
            for (int i = 0; i < CHUNK/(BLOCK/4); ++i) {
                const int r = kw + i*(BLOCK/4);
                if (r < rows) {
                    const float  xv = xs[base + r];
                    const float4 w  = *reinterpret_cast<const float4*>(buf + r*NCOL + jv*4);
                    acc.x = fmaf(xv, w.x, acc.x);
                    acc.y = fmaf(xv, w.y, acc.y);
                    acc.z = fmaf(xv, w.z, acc.z);
                    acc.w = fmaf(xv, w.w, acc.w);
                }
            }
        }
        if (++rs == NBUF) rs = 0;
    }

    // Warp reduce over the 8 kw groups inside each warp (lane bits 2..4)
    #pragma unroll
    for (int m = 4; m <= 16; m <<= 1) {
        acc.x += __shfl_xor_sync(0xffffffffu, acc.x, m);
        acc.y += __shfl_xor_sync(0xffffffffu, acc.y, m);
        acc.z += __shfl_xor_sync(0xffffffffu, acc.z, m);
        acc.w += __shfl_xor_sync(0xffffffffu, acc.w, m);
    }
    const int warp = tid >> 5;
    const int lane = tid & 31;
    if (lane < 4) red[warp][lane] = acc;
    __syncthreads();

    float4 r = make_float4(0.f, 0.f, 0.f, 0.f);
    if (tid < 32) {                    // warp 0 reduces 16 warp-partials
        const int wi = tid >> 2;
        const int j  = tid & 3;
        const float4 a = red[wi][j];
        const float4 b = red[wi + 8][j];
        r.x = a.x + b.x; r.y = a.y + b.y; r.z = a.z + b.z; r.w = a.w + b.w;
        #pragma unroll
        for (int m = 4; m <= 16; m <<= 1) {
            r.x += __shfl_xor_sync(0xffffffffu, r.x, m);
            r.y += __shfl_xor_sync(0xffffffffu, r.y, m);
            r.z += __shfl_xor_sync(0xffffffffu, r.z, m);
            r.w += __shfl_xor_sync(0xffffffffu, r.w, m);
        }
    }
    return r;   // valid for tid < 4
}

__device__ __forceinline__ void store_hidden(float4 r,
        const float* __restrict__ bias, int O, float* __restrict__ out,
        int j0, int tid)
{
    if (tid < 4 && j0 < O) {
        const float4 b = __ldg(reinterpret_cast<const float4*>(bias + j0) + tid);
        r.x = fmaxf(r.x + b.x, 0.f);
        r.y = fmaxf(r.y + b.y, 0.f);
        r.z = fmaxf(r.z + b.z, 0.f);
        r.w = fmaxf(r.w + b.w, 0.f);
        reinterpret_cast<float4*>(out + j0)[tid] = r;
    }
}

// ---------------------------------------------------------------------------
// Init: reset barrier counters, seed x0 (+te(1) tail) + row 0, precompute te.
// ---------------------------------------------------------------------------
__global__ void init_kernel(
    const float* __restrict__ start,
    const float* __restrict__ te_w1, const float* __restrict__ te_b1,
    const float* __restrict__ te_w2, const float* __restrict__ te_b2,
    float* __restrict__ out)
{
    const int b   = blockIdx.x;     // 0..255
    const int tid = threadIdx.x;    // 128 threads
    if (b == 0) {
        if (tid == 0) g_root = 0u;
        if (tid < LEAVES) g_leaf[tid] = 0u;
        for (int k = tid; k < GENE; k += TE) {
            const float v = start[k];
            g_x[0][k] = v;
            out[k]    = v;          // trajectory row 0
        }
    } else {
        const float t = (float)b * DT;
        __shared__ float h[TE];
        h[tid] = fmaxf(fmaf(t, te_w1[tid], te_b1[tid]), 0.f);
        __syncthreads();
        float acc = te_b2[tid];
        #pragma unroll 8
        for (int k = 0; k < TE; ++k)
            acc = fmaf(h[k], te_w2[k * TE + tid], acc);
        g_te[b][tid] = acc;
        if (b == 1) g_x[0][GENE + tid] = acc;   // te(1) tail for step 1
    }
}

// ---------------------------------------------------------------------------
// Persistent kernel: 255 Euler steps, 6 tree barriers/step, depth-4 cp.async
// weight streaming with 3-chunk cross-barrier lookahead.
// ---------------------------------------------------------------------------
__global__ void __launch_bounds__(BLOCK, 1) bridge_kernel(
    const float* __restrict__ w0, const float* __restrict__ b0,
    const float* __restrict__ w1, const float* __restrict__ b1,
    const float* __restrict__ w2, const float* __restrict__ b2,
    const float* __restrict__ w3, const float* __restrict__ b3,
    const float* __restrict__ w4, const float* __restrict__ b4,
    const float* __restrict__ wout, const float* __restrict__ bout,
    float* __restrict__ out)
{
    extern __shared__ float smem[];
    float* xs   = smem;                 // 2176 floats
    float* bufs = smem + 2176;          // NBUF * BUF_FLOATS
    __shared__ float4 red[16][4];

    const int tid = threadIdx.x;
    const int j0  = blockIdx.x * NCOL;
    unsigned nbar = 0;
    int is = 0, rs = 0;

    // Prologue: chunks 0..2 of step-1 layer0
    prefetch_chunk(w0, KIN, HID, j0, 0*CHUNK, bufs + 0*BUF_FLOATS, tid);
    prefetch_chunk(w0, KIN, HID, j0, 1*CHUNK, bufs + 1*BUF_FLOATS, tid);
    prefetch_chunk(w0, KIN, HID, j0, 2*CHUNK, bufs + 2*BUF_FLOATS, tid);
    is = 3;

    for (int t = 1; t < NSTEP; ++t) {
        const float* xprev = g_x[(t - 1) & 1];
        float*       xcur  = g_x[t & 1];
        float4 r;

        r = layer_core(w0, KIN, HID,  w1, HID, HID,  xprev,
                       xs, bufs, is, rs, red, j0, tid, nbar);
        store_hidden(r, b0, HID, g_h0, j0, tid);

        r = layer_core(w1, HID, HID,  w2, HID, HID,  g_h0,
                       xs, bufs, is, rs, red, j0, tid, nbar);
        store_hidden(r, b1, HID, g_h1, j0, tid);

        r = layer_core(w2, HID, HID,  w3, HID, HID,  g_h1,
                       xs, bufs, is, rs, red, j0, tid, nbar);
        store_hidden(r, b2, HID, g_h0, j0, tid);

        r = layer_core(w3, HID, HID,  w4, HID, HID,  g_h0,
                       xs, bufs, is, rs, red, j0, tid, nbar);
        store_hidden(r, b3, HID, g_h1, j0, tid);

        r = layer_core(w4, HID, HID,  wout, HID, GENE,  g_h1,
                       xs, bufs, is, rs, red, j0, tid, nbar);
        store_hidden(r, b4, HID, g_h0, j0, tid);

        // Final layer + Euler update + trajectory store
        r = layer_core(wout, HID, GENE,  w0, KIN, HID,  g_h0,
                       xs, bufs, is, rs, red, j0, tid, nbar);
        if (tid < 4 && j0 < GENE) {
            const float4 b  = __ldg(reinterpret_cast<const float4*>(bout + j0) + tid);
            const float4 xp = __ldcg(reinterpret_cast<const float4*>(xprev + j0) + tid);
            float4 xn;
            xn.x = fmaf(r.x + b.x, DT, xp.x);
            xn.y = fmaf(r.y + b.y, DT, xp.y);
            xn.z = fmaf(r.z + b.z, DT, xp.z);
            xn.w = fmaf(r.w + b.w, DT, xp.w);
            reinterpret_cast<float4*>(xcur + j0)[tid] = xn;
            __stcs(reinterpret_cast<float4*>(out + (size_t)t * GENE + j0) + tid, xn);
        }
        // tail CTA installs te(t+1) into xcur tail for next step's layer0
        if (blockIdx.x == GRID - 1 && t + 1 < NSTEP && tid < TE)
            xcur[GENE + tid] = g_te[t + 1][tid];
    }
}

extern "C" void kernel_launch(void* const* d_in, const int* in_sizes, int n_in,
                              void* d_out, int out_size)
{
    (void)in_sizes; (void)n_in; (void)out_size;
    const float* start  = (const float*)d_in[0];
    // d_in[1] = end_state (unused)
    const float* te_w1  = (const float*)d_in[2];
    const float* te_b1  = (const float*)d_in[3];
    const float* te_w2  = (const float*)d_in[4];
    const float* te_b2  = (const float*)d_in[5];
    const float* w0     = (const float*)d_in[6];
    const float* b0     = (const float*)d_in[7];
    const float* w1     = (const float*)d_in[8];
    const float* b1     = (const float*)d_in[9];
    const float* w2     = (const float*)d_in[10];
    const float* b2     = (const float*)d_in[11];
    const float* w3     = (const float*)d_in[12];
    const float* b3     = (const float*)d_in[13];
    const float* w4     = (const float*)d_in[14];
    const float* b4     = (const float*)d_in[15];
    const float* wout   = (const float*)d_in[16];
    const float* bout   = (const float*)d_in[17];
    float* out = (float*)d_out;

    cudaFuncSetAttribute(bridge_kernel,
                         cudaFuncAttributeMaxDynamicSharedMemorySize, SMEM_BYTES);

    init_kernel<<<NSTEP, TE>>>(start, te_w1, te_b1, te_w2, te_b2, out);
    bridge_kernel<<<GRID, BLOCK, SMEM_BYTES>>>(w0, b0, w1, b1, w2, b2, w3, b3,
                                               w4, b4, wout, bout, out);
}

// round 5
// speedup vs baseline: 1.6777x; 1.3886x over previous
#include <cuda_runtime.h>
#include <cstdint>

#define GENE   2000
#define TE     128
#define HID    2048
#define KIN    2128      // GENE + TE (time embedding lives in x tail)
#define NSTEP  256
#define GRID   128
#define BLOCK  512
#define NCOL   16        // output columns per CTA
#define DT     (1.0f/255.0f)
#define CHUNK  512
#define NBUF   4
#define LOOKAHEAD 3
#define BUF_FLOATS (CHUNK*NCOL)             // 8192 floats = 32 KB
#define SMEM_FLOATS (2176 + NBUF*BUF_FLOATS)
#define SMEM_BYTES  (SMEM_FLOATS*4)

// Replicated (permuted) weight layout: per-CTA slice contiguous.
//   layer 0   : 128 slices x (KIN *NCOL)
//   layer 1-4 : 128 slices x (HID *NCOL) each
//   layer out : 125 slices x (HID *NCOL)
#define OFF0   0L
#define OFF1   (OFF0 + 128L*KIN*NCOL)           // 4,358,144
#define OFF2   (OFF1 + 128L*HID*NCOL)
#define OFF3   (OFF2 + 128L*HID*NCOL)
#define OFF4   (OFF3 + 128L*HID*NCOL)
#define OFFO   (OFF4 + 128L*HID*NCOL)           // 21,135,360
#define TOTALF (OFFO + 125L*HID*NCOL)           // 25,231,360

// Persistent scratch (device globals: allocation is forbidden)
__device__ float    g_wrep[TOTALF];    // ~96 MB permuted weights
__device__ float    g_x[2][2176];      // x ping-pong: [0,2000)=x, [2000,2128)=te(t)
__device__ float    g_h0[HID];
__device__ float    g_h1[HID];
__device__ float    g_te[NSTEP][TE];   // precomputed time embeddings
__device__ unsigned g_count;           // grid-barrier monotonic counter

// ---------------------------------------------------------------------------
// Grid barrier: monotonic counter, release-arrive + acquire-spin.
// ---------------------------------------------------------------------------
__device__ __forceinline__ void grid_barrier(unsigned& nbar) {
    __syncthreads();
    ++nbar;
    if (threadIdx.x == 0) {
        __threadfence();
        asm volatile("red.release.gpu.add.u32 [%0], 1;" :: "l"(&g_count) : "memory");
        const unsigned target = nbar * GRID;
        unsigned cur;
        do {
            asm volatile("ld.acquire.gpu.u32 %0, [%1];" : "=r"(cur) : "l"(&g_count) : "memory");
        } while (cur < target);
    }
    __syncthreads();
}

// ---------------------------------------------------------------------------
// cp.async helpers
// ---------------------------------------------------------------------------
__device__ __forceinline__ void cp16(float* dst, const float* src) {
    unsigned a = (unsigned)__cvta_generic_to_shared(dst);
    asm volatile("cp.async.cg.shared.global [%0], [%1], 16;" :: "r"(a), "l"(src));
}

// One CHUNK-row slab of this CTA's contiguous slice -> smem buf.
// Fully contiguous: warp instruction = 512 consecutive bytes (4 full lines).
// Exactly one commit by all threads (uniform group counts).
__device__ __forceinline__ void prefetch_chunk(const float* __restrict__ slice,
        int K, int base, float* __restrict__ buf, int tid, bool active) {
    if (active) {
        const int lim = K * (NCOL/4);            // total float4s in slice
        const int s0  = base * (NCOL/4);         // first float4 of this chunk
        #pragma unroll
        for (int i = 0; i < (CHUNK*(NCOL/4))/BLOCK; ++i) {   // 4 segs/thread
            const int s = tid + i*BLOCK;
            if (s0 + s < lim)
                cp16(buf + s*4, slice + (long)(s0 + s)*4);
        }
    }
    asm volatile("cp.async.commit_group;");
}

// ---------------------------------------------------------------------------
// Layer. Invariant: on entry, this layer's chunks 0..2 are in flight (issued
// during the previous layer / prologue). During its nc iterations it issues
// its own chunks 3.., then chunks 0..2 of the NEXT layer.
// One wait_group + one __syncthreads per chunk. Result valid for tid<4.
// ---------------------------------------------------------------------------
__device__ __forceinline__ float4 layer_core(
    const float* __restrict__ slice,  int K,  bool act,
    const float* __restrict__ slicen, int Kn, bool actn,
    const float* __restrict__ in,
    float* __restrict__ xs, float* __restrict__ bufs,
    int& is, int& rs, float4 (*red)[4],
    int tid, unsigned& nbar)
{
    grid_barrier(nbar);

    // Stage input vector (fresh data from other SMs -> L2 path).
    const int K4 = K >> 2;
    for (int i = tid; i < K4; i += BLOCK)
        reinterpret_cast<float4*>(xs)[i] =
            __ldcg(reinterpret_cast<const float4*>(in) + i);

    const int kw = tid >> 2;
    const int jv = tid & 3;
    float4 acc = make_float4(0.f, 0.f, 0.f, 0.f);

    const int nc = (K + CHUNK - 1) / CHUNK;
    for (int c = 0; c < nc; ++c) {
        asm volatile("cp.async.wait_group 2;");   // chunk c landed
        __syncthreads();                          // ..and chunk c-1 reads done

        // Refill the buffer freed by the sync just passed.
        if (c < nc - LOOKAHEAD)
            prefetch_chunk(slice,  K,  (c + LOOKAHEAD)*CHUNK,
                           bufs + is*BUF_FLOATS, tid, act);
        else
            prefetch_chunk(slicen, Kn, (c - (nc - LOOKAHEAD))*CHUNK,
                           bufs + is*BUF_FLOATS, tid, actn);
        if (++is == NBUF) is = 0;

        if (act) {
            const float* __restrict__ buf = bufs + rs*BUF_FLOATS;
            const int base = c * CHUNK;
            const int rows = min(CHUNK, K - base);
            #pragma unroll
            for (int i = 0; i < CHUNK/(BLOCK/4); ++i) {
                const int r = kw + i*(BLOCK/4);
                if (r < rows) {
                    const float  xv = xs[base + r];
                    const float4 w  = *reinterpret_cast<const float4*>(buf + r*NCOL + jv*4);
                    acc.x = fmaf(xv, w.x, acc.x);
                    acc.y = fmaf(xv, w.y, acc.y);
                    acc.z = fmaf(xv, w.z, acc.z);
                    acc.w = fmaf(xv, w.w, acc.w);
                }
            }
        }
        if (++rs == NBUF) rs = 0;
    }

    // Warp reduce over the 8 kw groups inside each warp (lane bits 2..4)
    #pragma unroll
    for (int m = 4; m <= 16; m <<= 1) {
        acc.x += __shfl_xor_sync(0xffffffffu, acc.x, m);
        acc.y += __shfl_xor_sync(0xffffffffu, acc.y, m);
        acc.z += __shfl_xor_sync(0xffffffffu, acc.z, m);
        acc.w += __shfl_xor_sync(0xffffffffu, acc.w, m);
    }
    const int warp = tid >> 5;
    const int lane = tid & 31;
    if (lane < 4) red[warp][lane] = acc;
    __syncthreads();

    float4 r = make_float4(0.f, 0.f, 0.f, 0.f);
    if (tid < 32) {                    // warp 0 reduces 16 warp-partials
        const int wi = tid >> 2;
        const int j  = tid & 3;
        const float4 a = red[wi][j];
        const float4 b = red[wi + 8][j];
        r.x = a.x + b.x; r.y = a.y + b.y; r.z = a.z + b.z; r.w = a.w + b.w;
        #pragma unroll
        for (int m = 4; m <= 16; m <<= 1) {
            r.x += __shfl_xor_sync(0xffffffffu, r.x, m);
            r.y += __shfl_xor_sync(0xffffffffu, r.y, m);
            r.z += __shfl_xor_sync(0xffffffffu, r.z, m);
            r.w += __shfl_xor_sync(0xffffffffu, r.w, m);
        }
    }
    return r;   // valid for tid < 4
}

__device__ __forceinline__ void store_hidden(float4 r,
        const float* __restrict__ bias, float* __restrict__ out,
        int j0, int tid, bool act)
{
    if (tid < 4 && act) {
        const float4 b = __ldg(reinterpret_cast<const float4*>(bias + j0) + tid);
        r.x = fmaxf(r.x + b.x, 0.f);
        r.y = fmaxf(r.y + b.y, 0.f);
        r.z = fmaxf(r.z + b.z, 0.f);
        r.w = fmaxf(r.w + b.w, 0.f);
        reinterpret_cast<float4*>(out + j0)[tid] = r;
    }
}

// ---------------------------------------------------------------------------
// Weight reorg: permute each layer into per-CTA-slice-contiguous layout.
// dst[slice][r][c] = W[r][slice*NCOL + c].  Pure permutation (bit-exact).
// ---------------------------------------------------------------------------
__global__ void reorg_kernel(
    const float* __restrict__ w0, const float* __restrict__ w1,
    const float* __restrict__ w2, const float* __restrict__ w3,
    const float* __restrict__ w4, const float* __restrict__ wout)
{
    const int b = blockIdx.x;   // slice
    const int l = blockIdx.y;   // layer
    const float* W; int K, O; long off;
    switch (l) {
        case 0: W = w0;   K = KIN; O = HID;  off = OFF0; break;
        case 1: W = w1;   K = HID; O = HID;  off = OFF1; break;
        case 2: W = w2;   K = HID; O = HID;  off = OFF2; break;
        case 3: W = w3;   K = HID; O = HID;  off = OFF3; break;
        case 4: W = w4;   K = HID; O = HID;  off = OFF4; break;
        default:W = wout; K = HID; O = GENE; off = OFFO; break;
    }
    const int j0 = b * NCOL;
    if (j0 >= O) return;
    float4* dst = reinterpret_cast<float4*>(g_wrep + off + (long)b * K * NCOL);
    const int n4 = K * (NCOL/4);
    for (int e = threadIdx.x; e < n4; e += blockDim.x) {
        const int r  = e >> 2;           // row
        const int c4 = (e & 3) * 4;      // col within slice
        dst[e] = *reinterpret_cast<const float4*>(W + (long)r * O + j0 + c4);
    }
}

// ---------------------------------------------------------------------------
// Init: reset barrier counter, seed x0 (+te(1) tail) + row 0, precompute te.
// ---------------------------------------------------------------------------
__global__ void init_kernel(
    const float* __restrict__ start,
    const float* __restrict__ te_w1, const float* __restrict__ te_b1,
    const float* __restrict__ te_w2, const float* __restrict__ te_b2,
    float* __restrict__ out)
{
    const int b   = blockIdx.x;     // 0..255
    const int tid = threadIdx.x;    // 128 threads
    if (b == 0) {
        if (tid == 0) g_count = 0u;
        for (int k = tid; k < GENE; k += TE) {
            const float v = start[k];
            g_x[0][k] = v;
            out[k]    = v;          // trajectory row 0
        }
    } else {
        const float t = (float)b * DT;
        __shared__ float h[TE];
        h[tid] = fmaxf(fmaf(t, te_w1[tid], te_b1[tid]), 0.f);
        __syncthreads();
        float acc = te_b2[tid];
        #pragma unroll 8
        for (int k = 0; k < TE; ++k)
            acc = fmaf(h[k], te_w2[k * TE + tid], acc);
        g_te[b][tid] = acc;
        if (b == 1) g_x[0][GENE + tid] = acc;   // te(1) tail for step 1
    }
}

// ---------------------------------------------------------------------------
// Persistent kernel: 255 Euler steps, 6 barriers/step, depth-4 cp.async
// streaming of CONTIGUOUS per-CTA weight slices, 3-chunk cross-layer lookahead.
// ---------------------------------------------------------------------------
__global__ void __launch_bounds__(BLOCK, 1) bridge_kernel(
    const float* __restrict__ b0, const float* __restrict__ b1,
    const float* __restrict__ b2, const float* __restrict__ b3,
    const float* __restrict__ b4, const float* __restrict__ bout,
    float* __restrict__ out)
{
    extern __shared__ float smem[];
    float* xs   = smem;                 // 2176 floats
    float* bufs = smem + 2176;          // NBUF * BUF_FLOATS
    __shared__ float4 red[16][4];

    const int tid = threadIdx.x;
    const int b   = blockIdx.x;
    const int j0  = b * NCOL;
    const bool actO = (j0 < GENE);      // active in the output layer

    const float* s0 = g_wrep + OFF0 + (long)b * KIN * NCOL;
    const float* s1 = g_wrep + OFF1 + (long)b * HID * NCOL;
    const float* s2 = g_wrep + OFF2 + (long)b * HID * NCOL;
    const float* s3 = g_wrep + OFF3 + (long)b * HID * NCOL;
    const float* s4 = g_wrep + OFF4 + (long)b * HID * NCOL;
    const float* so = g_wrep + OFFO + (long)b * HID * NCOL;   // valid iff actO

    unsigned nbar = 0;
    int is = 0, rs = 0;

    // Prologue: chunks 0..2 of step-1 layer0
    prefetch_chunk(s0, KIN, 0*CHUNK, bufs + 0*BUF_FLOATS, tid, true);
    prefetch_chunk(s0, KIN, 1*CHUNK, bufs + 1*BUF_FLOATS, tid, true);
    prefetch_chunk(s0, KIN, 2*CHUNK, bufs + 2*BUF_FLOATS, tid, true);
    is = 3;

    for (int t = 1; t < NSTEP; ++t) {
        const float* xprev = g_x[(t - 1) & 1];
        float*       xcur  = g_x[t & 1];
        float4 r;

        r = layer_core(s0, KIN, true,  s1, HID, true,  xprev,
                       xs, bufs, is, rs, red, tid, nbar);
        store_hidden(r, b0, g_h0, j0, tid, true);

        r = layer_core(s1, HID, true,  s2, HID, true,  g_h0,
                       xs, bufs, is, rs, red, tid, nbar);
        store_hidden(r, b1, g_h1, j0, tid, true);

        r = layer_core(s2, HID, true,  s3, HID, true,  g_h1,
                       xs, bufs, is, rs, red, tid, nbar);
        store_hidden(r, b2, g_h0, j0, tid, true);

        r = layer_core(s3, HID, true,  s4, HID, true,  g_h0,
                       xs, bufs, is, rs, red, tid, nbar);
        store_hidden(r, b3, g_h1, j0, tid, true);

        r = layer_core(s4, HID, true,  so, HID, actO,  g_h1,
                       xs, bufs, is, rs, red, tid, nbar);
        store_hidden(r, b4, g_h0, j0, tid, true);

        // Final layer + Euler update + trajectory store
        r = layer_core(so, HID, actO,  s0, KIN, true,  g_h0,
                       xs, bufs, is, rs, red, tid, nbar);
        if (tid < 4 && actO) {
            const float4 bb = __ldg(reinterpret_cast<const float4*>(bout + j0) + tid);
            const float4 xp = __ldcg(reinterpret_cast<const float4*>(xprev + j0) + tid);
            float4 xn;
            xn.x = fmaf(r.x + bb.x, DT, xp.x);
            xn.y = fmaf(r.y + bb.y, DT, xp.y);
            xn.z = fmaf(r.z + bb.z, DT, xp.z);
            xn.w = fmaf(r.w + bb.w, DT, xp.w);
            reinterpret_cast<float4*>(xcur + j0)[tid] = xn;
            __stcs(reinterpret_cast<float4*>(out + (size_t)t * GENE + j0) + tid, xn);
        }
        // tail CTA installs te(t+1) into xcur tail for next step's layer0
        if (b == GRID - 1 && t + 1 < NSTEP && tid < TE)
            xcur[GENE + tid] = g_te[t + 1][tid];
    }
}

extern "C" void kernel_launch(void* const* d_in, const int* in_sizes, int n_in,
                              void* d_out, int out_size)
{
    (void)in_sizes; (void)n_in; (void)out_size;
    const float* start  = (const float*)d_in[0];
    // d_in[1] = end_state (unused)
    const float* te_w1  = (const float*)d_in[2];
    const float* te_b1  = (const float*)d_in[3];
    const float* te_w2  = (const float*)d_in[4];
    const float* te_b2  = (const float*)d_in[5];
    const float* w0     = (const float*)d_in[6];
    const float* b0     = (const float*)d_in[7];
    const float* w1     = (const float*)d_in[8];
    const float* b1     = (const float*)d_in[9];
    const float* w2     = (const float*)d_in[10];
    const float* b2     = (const float*)d_in[11];
    const float* w3     = (const float*)d_in[12];
    const float* b3     = (const float*)d_in[13];
    const float* w4     = (const float*)d_in[14];
    const float* b4     = (const float*)d_in[15];
    const float* wout   = (const float*)d_in[16];
    const float* bout   = (const float*)d_in[17];
    float* out = (float*)d_out;

    cudaFuncSetAttribute(bridge_kernel,
                         cudaFuncAttributeMaxDynamicSharedMemorySize, SMEM_BYTES);

    dim3 rg(GRID, 6);
    reorg_kernel<<<rg, 256>>>(w0, w1, w2, w3, w4, wout);
    init_kernel<<<NSTEP, TE>>>(start, te_w1, te_b1, te_w2, te_b2, out);
    bridge_kernel<<<GRID, BLOCK, SMEM_BYTES>>>(b0, b1, b2, b3, b4, bout, out);
}

// round 6
// speedup vs baseline: 2.0829x; 1.2415x over previous
#include <cuda_runtime.h>
#include <cuda_bf16.h>
#include <cstdint>

#define GENE   2000
#define TE     128
#define HID    2048
#define KIN    2128      // GENE + TE (time embedding lives in x tail)
#define NSTEP  256
#define GRID   128
#define BLOCK  512
#define NCOL   16        // output columns per CTA
#define DT     (1.0f/255.0f)
#define CHUNK  512
#define NBUF   5
#define LOOKAHEAD 4                         // chunks in flight; wait_group 3
#define BUF_BYTES (CHUNK*NCOL*2)            // 16 KB (bf16)
#define XS_FLOATS 2176
#define SMEM_BYTES (XS_FLOATS*4 + NBUF*BUF_BYTES)

// Permuted bf16 weights: per-CTA slice contiguous (elements, not bytes).
//   layer 0   : 128 slices x (KIN *NCOL)
//   layer 1-4 : 128 slices x (HID *NCOL) each
//   layer out : 125 slices x (HID *NCOL)
#define OFF0   0L
#define OFF1   (OFF0 + 128L*KIN*NCOL)
#define OFF2   (OFF1 + 128L*HID*NCOL)
#define OFF3   (OFF2 + 128L*HID*NCOL)
#define OFF4   (OFF3 + 128L*HID*NCOL)
#define OFFO   (OFF4 + 128L*HID*NCOL)
#define TOTALF (OFFO + 125L*HID*NCOL)       // ~25.2M elements = ~48 MB bf16

// Persistent scratch (device globals: allocation is forbidden)
__device__ __nv_bfloat16 g_wrep[TOTALF];   // permuted bf16 weights
__device__ float    g_x[2][2176];      // x ping-pong: [0,2000)=x, [2000,2128)=te(t)
__device__ float    g_h0[HID];
__device__ float    g_h1[HID];
__device__ float    g_te[NSTEP][TE];   // precomputed time embeddings
__device__ unsigned g_count;           // grid-barrier monotonic counter

// ---------------------------------------------------------------------------
// Grid barrier: monotonic counter, release-arrive + acquire-spin.
// ---------------------------------------------------------------------------
__device__ __forceinline__ void grid_barrier(unsigned& nbar) {
    __syncthreads();
    ++nbar;
    if (threadIdx.x == 0) {
        __threadfence();
        asm volatile("red.release.gpu.add.u32 [%0], 1;" :: "l"(&g_count) : "memory");
        const unsigned target = nbar * GRID;
        unsigned cur;
        do {
            asm volatile("ld.acquire.gpu.u32 %0, [%1];" : "=r"(cur) : "l"(&g_count) : "memory");
        } while (cur < target);
    }
    __syncthreads();
}

// ---------------------------------------------------------------------------
// cp.async helpers
// ---------------------------------------------------------------------------
__device__ __forceinline__ void cp16(char* dst, const char* src) {
    unsigned a = (unsigned)__cvta_generic_to_shared(dst);
    asm volatile("cp.async.cg.shared.global [%0], [%1], 16;" :: "r"(a), "l"(src));
}

// One CHUNK-row slab (bf16, contiguous) -> smem buf. One commit, all threads.
__device__ __forceinline__ void prefetch_chunk(const char* __restrict__ slice,
        int K, int base, char* __restrict__ buf, int tid, bool active) {
    if (active) {
        const int lim = K * 2;            // 16B segments in whole slice
        const int s0  = base * 2;         // first 16B segment of this chunk
        #pragma unroll
        for (int i = 0; i < (CHUNK*2)/BLOCK; ++i) {   // 2 segs/thread
            const int s = tid + i*BLOCK;
            if (s0 + s < lim)
                cp16(buf + s*16, slice + (long)(s0 + s)*16);
        }
    }
    asm volatile("cp.async.commit_group;");
}

// ---------------------------------------------------------------------------
// Layer. Invariant: on entry, this layer's chunks 0..LOOKAHEAD-1 are in
// flight. During its nc iterations it issues its remaining chunks, then
// chunks 0..LOOKAHEAD-1 of the NEXT layer. Requires nc >= LOOKAHEAD (min
// nc = 4 = LOOKAHEAD). One wait_group + one __syncthreads per chunk.
// Result valid for tid<4 (float4 at cols j0 + tid*4).
// ---------------------------------------------------------------------------
__device__ __forceinline__ float4 layer_core(
    const char* __restrict__ slice,  int K,  bool act,
    const char* __restrict__ slicen, int Kn, bool actn,
    const float* __restrict__ in,
    float* __restrict__ xs, char* __restrict__ bufs,
    int& is, int& rs, float4 (*red)[4],
    int tid, unsigned& nbar)
{
    grid_barrier(nbar);

    // Stage input vector (fresh data from other SMs -> L2 path).
    const int K4 = K >> 2;
    for (int i = tid; i < K4; i += BLOCK)
        reinterpret_cast<float4*>(xs)[i] =
            __ldcg(reinterpret_cast<const float4*>(in) + i);

    const int kw = tid >> 2;
    const int jv = tid & 3;
    float4 acc = make_float4(0.f, 0.f, 0.f, 0.f);

    const int nc = (K + CHUNK - 1) / CHUNK;
    for (int c = 0; c < nc; ++c) {
        asm volatile("cp.async.wait_group 3;");   // chunk c landed
        __syncthreads();                          // ..and chunk c-1 reads done

        // Refill the buffer freed by the sync just passed.
        if (c < nc - LOOKAHEAD)
            prefetch_chunk(slice,  K,  (c + LOOKAHEAD)*CHUNK,
                           bufs + is*BUF_BYTES, tid, act);
        else
            prefetch_chunk(slicen, Kn, (c - (nc - LOOKAHEAD))*CHUNK,
                           bufs + is*BUF_BYTES, tid, actn);
        if (++is == NBUF) is = 0;

        if (act) {
            const char* __restrict__ buf = bufs + rs*BUF_BYTES;
            const int base = c * CHUNK;
            const int rows = min(CHUNK, K - base);
            #pragma unroll
            for (int i = 0; i < CHUNK/(BLOCK/4); ++i) {
                const int r = kw + i*(BLOCK/4);
                if (r < rows) {
                    const float xv = xs[base + r];
                    const uint2 wv = *reinterpret_cast<const uint2*>(buf + r*32 + jv*8);
                    const float2 f0 = __bfloat1622float2(
                        *reinterpret_cast<const __nv_bfloat162*>(&wv.x));
                    const float2 f1 = __bfloat1622float2(
                        *reinterpret_cast<const __nv_bfloat162*>(&wv.y));
                    acc.x = fmaf(xv, f0.x, acc.x);
                    acc.y = fmaf(xv, f0.y, acc.y);
                    acc.z = fmaf(xv, f1.x, acc.z);
                    acc.w = fmaf(xv, f1.y, acc.w);
                }
            }
        }
        if (++rs == NBUF) rs = 0;
    }

    // Warp reduce over the 8 kw groups inside each warp (lane bits 2..4)
    #pragma unroll
    for (int m = 4; m <= 16; m <<= 1) {
        acc.x += __shfl_xor_sync(0xffffffffu, acc.x, m);
        acc.y += __shfl_xor_sync(0xffffffffu, acc.y, m);
        acc.z += __shfl_xor_sync(0xffffffffu, acc.z, m);
        acc.w += __shfl_xor_sync(0xffffffffu, acc.w, m);
    }
    const int warp = tid >> 5;
    const int lane = tid & 31;
    if (lane < 4) red[warp][lane] = acc;
    __syncthreads();

    float4 r = make_float4(0.f, 0.f, 0.f, 0.f);
    if (tid < 32) {                    // warp 0 reduces 16 warp-partials
        const int wi = tid >> 2;
        const int j  = tid & 3;
        const float4 a = red[wi][j];
        const float4 b = red[wi + 8][j];
        r.x = a.x + b.x; r.y = a.y + b.y; r.z = a.z + b.z; r.w = a.w + b.w;
        #pragma unroll
        for (int m = 4; m <= 16; m <<= 1) {
            r.x += __shfl_xor_sync(0xffffffffu, r.x, m);
            r.y += __shfl_xor_sync(0xffffffffu, r.y, m);
            r.z += __shfl_xor_sync(0xffffffffu, r.z, m);
            r.w += __shfl_xor_sync(0xffffffffu, r.w, m);
        }
    }
    return r;   // valid for tid < 4
}

__device__ __forceinline__ void store_hidden(float4 r,
        const float* __restrict__ bias, float* __restrict__ out,
        int j0, int tid)
{
    if (tid < 4) {
        const float4 b = __ldg(reinterpret_cast<const float4*>(bias + j0) + tid);
        r.x = fmaxf(r.x + b.x, 0.f);
        r.y = fmaxf(r.y + b.y, 0.f);
        r.z = fmaxf(r.z + b.z, 0.f);
        r.w = fmaxf(r.w + b.w, 0.f);
        reinterpret_cast<float4*>(out + j0)[tid] = r;
    }
}

// ---------------------------------------------------------------------------
// Weight reorg: permute + convert fp32 -> bf16, per-CTA-slice contiguous.
// dst[slice][r][c] = bf16(W[r][slice*NCOL + c]).
// ---------------------------------------------------------------------------
__global__ void reorg_kernel(
    const float* __restrict__ w0, const float* __restrict__ w1,
    const float* __restrict__ w2, const float* __restrict__ w3,
    const float* __restrict__ w4, const float* __restrict__ wout)
{
    const int b = blockIdx.x;   // slice
    const int l = blockIdx.y;   // layer
    const float* W; int K, O; long off;
    switch (l) {
        case 0: W = w0;   K = KIN; O = HID;  off = OFF0; break;
        case 1: W = w1;   K = HID; O = HID;  off = OFF1; break;
        case 2: W = w2;   K = HID; O = HID;  off = OFF2; break;
        case 3: W = w3;   K = HID; O = HID;  off = OFF3; break;
        case 4: W = w4;   K = HID; O = HID;  off = OFF4; break;
        default:W = wout; K = HID; O = GENE; off = OFFO; break;
    }
    const int j0 = b * NCOL;
    if (j0 >= O) return;
    __nv_bfloat16* dst = g_wrep + off + (long)b * K * NCOL;
    const int n4 = K * (NCOL/4);
    for (int e = threadIdx.x; e < n4; e += blockDim.x) {
        const int r  = e >> 2;           // row
        const int c4 = (e & 3) * 4;      // col within slice
        const float4 w = *reinterpret_cast<const float4*>(W + (long)r * O + j0 + c4);
        uint2 p;
        __nv_bfloat162 p0 = __float22bfloat162_rn(make_float2(w.x, w.y));
        __nv_bfloat162 p1 = __float22bfloat162_rn(make_float2(w.z, w.w));
        p.x = *reinterpret_cast<unsigned*>(&p0);
        p.y = *reinterpret_cast<unsigned*>(&p1);
        *reinterpret_cast<uint2*>(dst + (long)e * 4) = p;
    }
}

// ---------------------------------------------------------------------------
// Init: reset barrier counter, seed x0 (+te(1) tail) + row 0, precompute te.
// ---------------------------------------------------------------------------
__global__ void init_kernel(
    const float* __restrict__ start,
    const float* __restrict__ te_w1, const float* __restrict__ te_b1,
    const float* __restrict__ te_w2, const float* __restrict__ te_b2,
    float* __restrict__ out)
{
    const int b   = blockIdx.x;     // 0..255
    const int tid = threadIdx.x;    // 128 threads
    if (b == 0) {
        if (tid == 0) g_count = 0u;
        for (int k = tid; k < GENE; k += TE) {
            const float v = start[k];
            g_x[0][k] = v;
            out[k]    = v;          // trajectory row 0
        }
    } else {
        const float t = (float)b * DT;
        __shared__ float h[TE];
        h[tid] = fmaxf(fmaf(t, te_w1[tid], te_b1[tid]), 0.f);
        __syncthreads();
        float acc = te_b2[tid];
        #pragma unroll 8
        for (int k = 0; k < TE; ++k)
            acc = fmaf(h[k], te_w2[k * TE + tid], acc);
        g_te[b][tid] = acc;
        if (b == 1) g_x[0][GENE + tid] = acc;   // te(1) tail for step 1
    }
}

// ---------------------------------------------------------------------------
// Persistent kernel: 255 Euler steps, 6 barriers/step, depth-5 cp.async
// streaming of contiguous bf16 weight slices, 4-chunk cross-layer lookahead.
// ---------------------------------------------------------------------------
__global__ void __launch_bounds__(BLOCK, 1) bridge_kernel(
    const float* __restrict__ b0, const float* __restrict__ b1,
    const float* __restrict__ b2, const float* __restrict__ b3,
    const float* __restrict__ b4, const float* __restrict__ bout,
    float* __restrict__ out)
{
    extern __shared__ float smem[];
    float* xs   = smem;                                 // 2176 floats
    char*  bufs = reinterpret_cast<char*>(smem + XS_FLOATS);
    __shared__ float4 red[16][4];

    const int tid = threadIdx.x;
    const int b   = blockIdx.x;
    const int j0  = b * NCOL;
    const bool actO = (j0 < GENE);      // active in the output layer

    const char* s0 = reinterpret_cast<const char*>(g_wrep + OFF0 + (long)b * KIN * NCOL);
    const char* s1 = reinterpret_cast<const char*>(g_wrep + OFF1 + (long)b * HID * NCOL);
    const char* s2 = reinterpret_cast<const char*>(g_wrep + OFF2 + (long)b * HID * NCOL);
    const char* s3 = reinterpret_cast<const char*>(g_wrep + OFF3 + (long)b * HID * NCOL);
    const char* s4 = reinterpret_cast<const char*>(g_wrep + OFF4 + (long)b * HID * NCOL);
    const char* so = reinterpret_cast<const char*>(g_wrep + OFFO + (long)b * HID * NCOL);

    unsigned nbar = 0;
    int is = 0, rs = 0;

    // Prologue: chunks 0..3 of step-1 layer0
    #pragma unroll
    for (int c = 0; c < LOOKAHEAD; ++c)
        prefetch_chunk(s0, KIN, c*CHUNK, bufs + c*BUF_BYTES, tid, true);
    is = LOOKAHEAD;

    for (int t = 1; t < NSTEP; ++t) {
        const float* xprev = g_x[(t - 1) & 1];
        float*       xcur  = g_x[t & 1];
        float4 r;

        r = layer_core(s0, KIN, true,  s1, HID, true,  xprev,
                       xs, bufs, is, rs, red, tid, nbar);
        store_hidden(r, b0, g_h0, j0, tid);

        r = layer_core(s1, HID, true,  s2, HID, true,  g_h0,
                       xs, bufs, is, rs, red, tid, nbar);
        store_hidden(r, b1, g_h1, j0, tid);

        r = layer_core(s2, HID, true,  s3, HID, true,  g_h1,
                       xs, bufs, is, rs, red, tid, nbar);
        store_hidden(r, b2, g_h0, j0, tid);

        r = layer_core(s3, HID, true,  s4, HID, true,  g_h0,
                       xs, bufs, is, rs, red, tid, nbar);
        store_hidden(r, b3, g_h1, j0, tid);

        r = layer_core(s4, HID, true,  so, HID, actO,  g_h1,
                       xs, bufs, is, rs, red, tid, nbar);
        store_hidden(r, b4, g_h0, j0, tid);

        // Final layer + Euler update + trajectory store
        r = layer_core(so, HID, actO,  s0, KIN, true,  g_h0,
                       xs, bufs, is, rs, red, tid, nbar);
        if (tid < 4 && actO) {
            const float4 bb = __ldg(reinterpret_cast<const float4*>(bout + j0) + tid);
            const float4 xp = __ldcg(reinterpret_cast<const float4*>(xprev + j0) + tid);
            float4 xn;
            xn.x = fmaf(r.x + bb.x, DT, xp.x);
            xn.y = fmaf(r.y + bb.y, DT, xp.y);
            xn.z = fmaf(r.z + bb.z, DT, xp.z);
            xn.w = fmaf(r.w + bb.w, DT, xp.w);
            reinterpret_cast<float4*>(xcur + j0)[tid] = xn;
            __stcs(reinterpret_cast<float4*>(out + (size_t)t * GENE + j0) + tid, xn);
        }
        // tail CTA installs te(t+1) into xcur tail for next step's layer0
        if (b == GRID - 1 && t + 1 < NSTEP && tid < TE)
            xcur[GENE + tid] = g_te[t + 1][tid];
    }
}

extern "C" void kernel_launch(void* const* d_in, const int* in_sizes, int n_in,
                              void* d_out, int out_size)
{
    (void)in_sizes; (void)n_in; (void)out_size;
    const float* start  = (const float*)d_in[0];
    // d_in[1] = end_state (unused)
    const float* te_w1  = (const float*)d_in[2];
    const float* te_b1  = (const float*)d_in[3];
    const float* te_w2  = (const float*)d_in[4];
    const float* te_b2  = (const float*)d_in[5];
    const float* w0     = (const float*)d_in[6];
    const float* b0     = (const float*)d_in[7];
    const float* w1     = (const float*)d_in[8];
    const float* b1     = (const float*)d_in[9];
    const float* w2     = (const float*)d_in[10];
    const float* b2     = (const float*)d_in[11];
    const float* w3     = (const float*)d_in[12];
    const float* b3     = (const float*)d_in[13];
    const float* w4     = (const float*)d_in[14];
    const float* b4     = (const float*)d_in[15];
    const float* wout   = (const float*)d_in[16];
    const float* bout   = (const float*)d_in[17];
    float* out = (float*)d_out;

    cudaFuncSetAttribute(bridge_kernel,
                         cudaFuncAttributeMaxDynamicSharedMemorySize, SMEM_BYTES);

    dim3 rg(GRID, 6);
    reorg_kernel<<<rg, 256>>>(w0, w1, w2, w3, w4, wout);
    init_kernel<<<NSTEP, TE>>>(start, te_w1, te_b1, te_w2, te_b2, out);
    bridge_kernel<<<GRID, BLOCK, SMEM_BYTES>>>(b0, b1, b2, b3, b4, bout, out);
}